// round 14
// baseline (speedup 1.0000x reference)
#include <cuda_runtime.h>
#include <cuda_fp16.h>
#include <cstdint>

#define BSZ 256
#define HID 4096
#define NIN 1024
#define NOUT 10
#define STEPS_TOTAL 25
#define STEPS_FREE 20
#define OUTW (2 * HID + NOUT)   // 8202
#define NTHREADS 128

// GEMM tiling: BM=BN=128, BK=64 halfs per iter, 4 warps, warp tile 64x64
#define BKK 64
#define NSTAGE 4
#define ROWH 72                            // smem row stride in halfs (144 B)
#define STAGE_HALFS (2 * 128 * ROWH)       // A + B tiles
#define SMEM_BYTES (NSTAGE * STAGE_HALFS * 2)  // 147456 B

// ---------------- persistent device scratch ----------------
__device__ __align__(128) __half g_rx[BSZ * NIN];
__device__ __align__(128) float  g_c0[BSZ * HID];
__device__ __align__(128) __half g_c0q[BSZ * HID];      // 0.25*c0, fp16
__device__ __align__(128) __half g_s1[2][BSZ * HID];
__device__ __align__(128) __half g_s2[2][BSZ * HID];
__device__ __align__(128) float  g_s3[2][BSZ * NOUT];
__device__ __align__(128) __half g_fw0T[(size_t)HID * NIN];
__device__ __align__(128) __half g_fw1T[(size_t)HID * HID];
__device__ __align__(128) __half g_bw1T[(size_t)HID * HID];

// ---------------- helpers ----------------
__device__ __forceinline__ uint32_t smem_u32(const void* p) {
    uint32_t a;
    asm("{ .reg .u64 t; cvta.to.shared.u64 t, %1; cvt.u32.u64 %0, t; }"
        : "=r"(a) : "l"(p));
    return a;
}

__device__ __forceinline__ void cp16(uint32_t dst, const void* src) {
    asm volatile("cp.async.cg.shared.global [%0], [%1], 16;"
                 :: "r"(dst), "l"(src) : "memory");
}
#define CP_COMMIT() asm volatile("cp.async.commit_group;" ::: "memory")
#define CP_WAIT(n)  asm volatile("cp.async.wait_group %0;" :: "n"(n) : "memory")

__device__ __forceinline__ void ldsm4(uint32_t& r0, uint32_t& r1,
                                      uint32_t& r2, uint32_t& r3, uint32_t addr) {
    asm volatile("ldmatrix.sync.aligned.m8n8.x4.shared.b16 {%0,%1,%2,%3}, [%4];"
                 : "=r"(r0), "=r"(r1), "=r"(r2), "=r"(r3) : "r"(addr));
}

// m16n8k16 fp16 mma, fp32 accum
__device__ __forceinline__ void mma_f16(float* c, const uint32_t* a,
                                        uint32_t b0, uint32_t b1) {
    asm volatile(
        "mma.sync.aligned.m16n8k16.row.col.f32.f16.f16.f32 "
        "{%0,%1,%2,%3}, {%4,%5,%6,%7}, {%8,%9}, {%0,%1,%2,%3};"
        : "+f"(c[0]), "+f"(c[1]), "+f"(c[2]), "+f"(c[3])
        : "r"(a[0]), "r"(a[1]), "r"(a[2]), "r"(a[3]), "r"(b0), "r"(b1));
}

// ---------------- GEMM tile (device) ----------------
// [128,128] tile at (rowBase,colBase) of D[M,4096] = A[M,K] @ BT[4096,K]^T
// 4 warps: warpM = wid&1 (2 row-groups of 64), warpN = wid>>1 (2 col-groups of 64)
// MODE 0: OutF = acc (fp32)                                   (c0)
// MODE 1: v = clip(0.5*Sold + C0q + 0.25*acc)                 (s1; C0q = 0.25*c0)
// MODE 2: v = clip(0.5*Sold + 0.25*(acc + s3old@bw2))         (s2)
// FINAL=false: OutH = h(v);  FINAL=true: fOut[row*OUTW + fColOff + col] = v (fp32)
template <int MODE, bool FINAL>
__device__ __forceinline__ void gemm_tile(
    const __half* __restrict__ A, const __half* __restrict__ BT, int K,
    float* __restrict__ OutF, __half* __restrict__ OutH,
    const __half* __restrict__ Sold, const __half* __restrict__ C0q,
    const float* __restrict__ s3old, const float* __restrict__ bw2,
    float* __restrict__ fOut, int fColOff,
    int rowBase, int colBase, __half* smem)
{
    const int tid  = threadIdx.x;
    const int lane = tid & 31;
    const int wid  = tid >> 5;              // 0..3
    const int g = lane >> 2, q = lane & 3;
    const int warpM = wid & 1;              // 2 row-groups of 64
    const int warpN = wid >> 1;             // 2 col-groups of 64

    float acc[4][8][4];
#pragma unroll
    for (int mi = 0; mi < 4; mi++)
#pragma unroll
        for (int nj = 0; nj < 8; nj++)
#pragma unroll
            for (int t = 0; t < 4; t++) acc[mi][nj][t] = 0.0f;

    // loaders: 128 threads; each thread owns one A row and one B row (8 cp16 each)
    const __half* Ag = A  + (size_t)(rowBase + tid) * K;
    const __half* Bg = BT + (size_t)(colBase + tid) * K;

    const int nIt = K / BKK;

#define LOAD_STAGE(s, kt)                                            \
    do {                                                             \
        __half* As_ = smem + (s) * STAGE_HALFS;                      \
        __half* Bs_ = As_ + 128 * ROWH;                              \
        uint32_t dA = smem_u32(As_ + tid * ROWH);                    \
        uint32_t dB = smem_u32(Bs_ + tid * ROWH);                    \
        _Pragma("unroll")                                            \
        for (int u = 0; u < 8; u++) {                                \
            cp16(dA + u * 16, Ag + (kt) + u * 8);                    \
            cp16(dB + u * 16, Bg + (kt) + u * 8);                    \
        }                                                            \
    } while (0)

    LOAD_STAGE(0, 0);       CP_COMMIT();
    LOAD_STAGE(1, BKK);     CP_COMMIT();
    LOAD_STAGE(2, 2 * BKK); CP_COMMIT();

    const int lrow = (lane & 7) + ((lane >> 3) & 1) * 8;
    const int lcolB = ((lane >> 4) & 1) * 16;   // bytes

    uint32_t a[2][4][4];   // [buf][mi][frag]
    uint32_t b[2][4][4];   // [buf][jb][frag]

#define LOAD_FRAGS(buf, aB, bB, ko)                                          \
    do {                                                                     \
        _Pragma("unroll")                                                    \
        for (int mi = 0; mi < 4; mi++)                                       \
            ldsm4(a[buf][mi][0], a[buf][mi][1], a[buf][mi][2], a[buf][mi][3],\
                  (aB) + mi * 16 * (ROWH * 2) + (ko));                       \
        _Pragma("unroll")                                                    \
        for (int jb = 0; jb < 4; jb++)                                       \
            ldsm4(b[buf][jb][0], b[buf][jb][1], b[buf][jb][2], b[buf][jb][3],\
                  (bB) + jb * 16 * (ROWH * 2) + (ko));                       \
    } while (0)

#define DO_MMA(buf)                                                          \
    do {                                                                     \
        _Pragma("unroll")                                                    \
        for (int jb = 0; jb < 4; jb++) {                                     \
            _Pragma("unroll")                                                \
            for (int mi = 0; mi < 4; mi++) {                                 \
                mma_f16(acc[mi][jb * 2 + 0], a[buf][mi],                     \
                        b[buf][jb][0], b[buf][jb][2]);                       \
                mma_f16(acc[mi][jb * 2 + 1], a[buf][mi],                     \
                        b[buf][jb][1], b[buf][jb][3]);                       \
            }                                                                \
        }                                                                    \
    } while (0)

    // prime: wait for stage 0, load its first k-step fragments
    CP_WAIT(2);
    __syncthreads();
    {
        const __half* As = smem;
        const __half* Bs = As + 128 * ROWH;
        const uint32_t aB = smem_u32(As + (warpM * 64 + lrow) * ROWH) + lcolB;
        const uint32_t bB = smem_u32(Bs + (warpN * 64 + lrow) * ROWH) + lcolB;
        LOAD_FRAGS(0, aB, bB, 0);
    }

    for (int it = 0; it < nIt; ++it) {
        if (it + 3 < nIt) {
            LOAD_STAGE((it + 3) & (NSTAGE - 1), (it + 3) * BKK);
        }
        CP_COMMIT();

        const __half* As = smem + (it & (NSTAGE - 1)) * STAGE_HALFS;
        const __half* Bs = As + 128 * ROWH;
        const uint32_t aB = smem_u32(As + (warpM * 64 + lrow) * ROWH) + lcolB;
        const uint32_t bB = smem_u32(Bs + (warpN * 64 + lrow) * ROWH) + lcolB;

        // k-steps 0..2: prefetch ks+1 into other buffer, then mma current
#pragma unroll
        for (int ks = 0; ks < 3; ks++) {
            LOAD_FRAGS((ks + 1) & 1, aB, bB, (ks + 1) * 32);
            DO_MMA(ks & 1);
        }

        // boundary: advance smem pipeline, prefetch next stage's k-step 0
        if (it + 1 < nIt) {
            CP_WAIT(2);
            __syncthreads();
            const __half* As2 = smem + ((it + 1) & (NSTAGE - 1)) * STAGE_HALFS;
            const __half* Bs2 = As2 + 128 * ROWH;
            const uint32_t aB2 = smem_u32(As2 + (warpM * 64 + lrow) * ROWH) + lcolB;
            const uint32_t bB2 = smem_u32(Bs2 + (warpN * 64 + lrow) * ROWH) + lcolB;
            LOAD_FRAGS(0, aB2, bB2, 0);
        }
        DO_MMA(1);   // k-step 3 lives in buffer 1
    }
#undef LOAD_FRAGS
#undef DO_MMA
#undef LOAD_STAGE

    // ---------------- epilogue ----------------
    const int rw = rowBase + warpM * 64;
    const int cw = colBase + warpN * 64;

#pragma unroll
    for (int mi = 0; mi < 4; mi++) {
        if (MODE == 2) {
            // fold in s3old @ bw2 (K = 10) for this mi's two 8-row groups
            float s3r[2][10];
#pragma unroll
            for (int h = 0; h < 2; h++) {
                const int r = rw + mi * 16 + h * 8 + g;
#pragma unroll
                for (int k = 0; k < NOUT; k++)
                    s3r[h][k] = s3old[r * NOUT + k];
            }
#pragma unroll
            for (int nj = 0; nj < 8; nj++) {
                const int cb = cw + nj * 8 + q * 2;
#pragma unroll
                for (int k = 0; k < NOUT; k++) {
                    const float2 b2 = *(const float2*)&bw2[(size_t)k * HID + cb];
                    acc[mi][nj][0] = fmaf(s3r[0][k], b2.x, acc[mi][nj][0]);
                    acc[mi][nj][1] = fmaf(s3r[0][k], b2.y, acc[mi][nj][1]);
                    acc[mi][nj][2] = fmaf(s3r[1][k], b2.x, acc[mi][nj][2]);
                    acc[mi][nj][3] = fmaf(s3r[1][k], b2.y, acc[mi][nj][3]);
                }
            }
        }

#pragma unroll
        for (int nj = 0; nj < 8; nj++) {
            const int cb = cw + nj * 8 + q * 2;
#pragma unroll
            for (int h = 0; h < 2; h++) {
                const int row = rw + mi * 16 + h * 8 + g;
                const size_t idx = (size_t)row * HID + cb;
                float vx = acc[mi][nj][h * 2 + 0];
                float vy = acc[mi][nj][h * 2 + 1];
                if (MODE == 0) {
                    *(float2*)&OutF[idx] = make_float2(vx, vy);
                } else {
                    const float2 so = __half22float2(*(const __half2*)&Sold[idx]);
                    if (MODE == 1) {
                        const float2 c2 = __half22float2(*(const __half2*)&C0q[idx]);
                        vx = 0.5f * so.x + c2.x + 0.25f * vx;
                        vy = 0.5f * so.y + c2.y + 0.25f * vy;
                    } else {
                        vx = 0.5f * so.x + 0.25f * vx;
                        vy = 0.5f * so.y + 0.25f * vy;
                    }
                    vx = fminf(fmaxf(vx, 0.0f), 1.0f);
                    vy = fminf(fmaxf(vy, 0.0f), 1.0f);
                    if (FINAL) {
                        *(float2*)&fOut[(size_t)row * OUTW + fColOff + cb] =
                            make_float2(vx, vy);
                    } else {
                        *(__half2*)&OutH[idx] = __floats2half2_rn(vx, vy);
                    }
                }
            }
        }
    }
}

// ---------------- s3 tile (device): 32 rows, 128 threads (8 rows/warp) ----------------
template <bool FINAL>
__device__ __forceinline__ void s3_tile(
    const __half* __restrict__ s2old, const float* __restrict__ fw2,
    const float* __restrict__ s3old, const float* __restrict__ y,
    float* __restrict__ s3new, float* __restrict__ fOut,
    int weak, int rowBase, __half* smem_raw)
{
    const int tid = threadIdx.x, lane = tid & 31, wid = tid >> 5;   // 4 warps
    float* fs = (float*)smem_raw;
    float acc[8][NOUT];
#pragma unroll
    for (int r = 0; r < 8; r++)
#pragma unroll
        for (int j = 0; j < NOUT; j++) acc[r][j] = 0.0f;

    for (int c = 0; c < 8; c++) {
        __syncthreads();
        for (int i = tid; i < 512 * NOUT; i += NTHREADS) {
            int kl = i / NOUT, j = i - kl * NOUT;
            fs[kl * 11 + j] = fw2[(size_t)(c * 512 + kl) * NOUT + j];
        }
        __syncthreads();
#pragma unroll
        for (int r = 0; r < 8; r++) {
            const int row = rowBase + wid * 8 + r;
            const __half* s2r = s2old + (size_t)row * HID + c * 512;
#pragma unroll 4
            for (int i = 0; i < 16; i++) {
                const int kl = lane + i * 32;
                const float sv = __half2float(s2r[kl]);
#pragma unroll
                for (int j = 0; j < NOUT; j++)
                    acc[r][j] = fmaf(sv, fs[kl * 11 + j], acc[r][j]);
            }
        }
    }

#pragma unroll
    for (int r = 0; r < 8; r++) {
        const int row = rowBase + wid * 8 + r;
#pragma unroll
        for (int j = 0; j < NOUT; j++) {
            float v = acc[r][j];
#pragma unroll
            for (int o = 16; o; o >>= 1) v += __shfl_xor_sync(0xffffffffu, v, o);
            if (lane == 0) {
                float out = weak ? 0.5f * (v + y[row * NOUT + j])
                                 : 0.5f * (s3old[row * NOUT + j] + v);
                out = fminf(fmaxf(out, 0.0f), 1.0f);
                if (FINAL) fOut[(size_t)row * OUTW + 2 * HID + j] = out;
                else       s3new[row * NOUT + j] = out;
            }
        }
    }
}

// ---------------- fused step kernel: 136 CTAs = one wave ----------------
template <bool FINAL>
__global__ __launch_bounds__(NTHREADS, 1) void step_kernel(
    const __half* __restrict__ s1old, const __half* __restrict__ s2old,
    const float* __restrict__ s3old,
    __half* __restrict__ s1new, __half* __restrict__ s2new, float* __restrict__ s3new,
    const __half* __restrict__ fw1T, const __half* __restrict__ bw1T,
    const float* __restrict__ bw2, const float* __restrict__ fw2,
    const __half* __restrict__ c0q, const float* __restrict__ y,
    float* __restrict__ fOut, int weak)
{
    extern __shared__ __half smem[];
    const int bid = blockIdx.x;
    if (bid < 64) {
        gemm_tile<1, FINAL>(s2old, bw1T, HID, nullptr, s1new, s1old, c0q, nullptr,
                            nullptr, fOut, 0,
                            (bid >> 5) * 128, (bid & 31) * 128, smem);
    } else if (bid < 128) {
        const int t = bid - 64;
        gemm_tile<2, FINAL>(s1old, fw1T, HID, nullptr, s2new, s2old, nullptr, s3old,
                            bw2, fOut, HID,
                            (t >> 5) * 128, (t & 31) * 128, smem);
    } else {
        s3_tile<FINAL>(s2old, fw2, s3old, y, s3new, fOut, weak, (bid - 128) * 32, smem);
    }
}

__global__ __launch_bounds__(NTHREADS, 1) void c0_kernel(
    const __half* __restrict__ rx, const __half* __restrict__ fw0T,
    float* __restrict__ c0)
{
    extern __shared__ __half smem[];
    const int bid = blockIdx.x;
    gemm_tile<0, false>(rx, fw0T, NIN, c0, nullptr, nullptr, nullptr, nullptr,
                        nullptr, nullptr, 0,
                        (bid >> 5) * 128, (bid & 31) * 128, smem);
}

// ---------------- small kernels ----------------
__global__ void clip_kernel(const float* __restrict__ x, __half* __restrict__ rx, int n) {
    int i = blockIdx.x * blockDim.x + threadIdx.x;
    if (i < n) rx[i] = __float2half_rn(fminf(fmaxf(x[i], 0.0f), 1.0f));
}

__global__ void init_kernel(const float* __restrict__ c0, __half* __restrict__ c0q,
                            __half* __restrict__ s1, __half* __restrict__ s2,
                            float* __restrict__ s3) {
    int i = blockIdx.x * blockDim.x + threadIdx.x;
    if (i < BSZ * HID) {
        float qc = 0.25f * c0[i];
        c0q[i] = __float2half_rn(qc);
        s1[i] = __float2half_rn(fminf(fmaxf(qc, 0.0f), 1.0f));
        s2[i] = __half(0.0f);
    }
    if (i < BSZ * NOUT) s3[i] = 0.0f;
}

// 64x64-tile transpose+convert: dst[c][r] = h(src[r][c]); full-width fp16 stores.
__global__ void transpose64_kernel(const float* __restrict__ src,
                                   __half* __restrict__ dst, int R, int C) {
    __shared__ float tile[64][65];
    const int bx = blockIdx.x * 64;
    const int by = blockIdx.y * 64;
    const int tx = threadIdx.x, ty = threadIdx.y;
#pragma unroll
    for (int j = 0; j < 2; j++)
#pragma unroll
        for (int i = 0; i < 8; i++)
            tile[ty + i * 8][tx + j * 32] =
                src[(size_t)(by + ty + i * 8) * C + bx + tx + j * 32];
    __syncthreads();
#pragma unroll
    for (int i = 0; i < 8; i++) {
        const int cc = bx + ty + i * 8;
        const int k = ty + i * 8;
        __half2 v = __floats2half2_rn(tile[tx * 2][k], tile[tx * 2 + 1][k]);
        *(__half2*)&dst[(size_t)cc * R + by + tx * 2] = v;
    }
}

// ---------------- launch ----------------
extern "C" void kernel_launch(void* const* d_in, const int* in_sizes, int n_in,
                              void* d_out, int out_size)
{
    const float* x   = (const float*)d_in[0];
    const float* fw0 = (const float*)d_in[1];
    const float* fw1 = (const float*)d_in[2];
    const float* fw2 = (const float*)d_in[3];
    // d_in[4] = bw0 (unused by the dynamics)
    const float* bw1 = (const float*)d_in[5];
    const float* bw2 = (const float*)d_in[6];
    const float* y   = (const float*)d_in[7];
    float* out = (float*)d_out;

    cudaFuncSetAttribute(step_kernel<false>, cudaFuncAttributeMaxDynamicSharedMemorySize, SMEM_BYTES);
    cudaFuncSetAttribute(step_kernel<true>,  cudaFuncAttributeMaxDynamicSharedMemorySize, SMEM_BYTES);
    cudaFuncSetAttribute(c0_kernel,          cudaFuncAttributeMaxDynamicSharedMemorySize, SMEM_BYTES);

    __half *rx, *c0q, *s1base, *s2base, *fw0T, *fw1T, *bw1T;
    float *c0, *s3base;
    cudaGetSymbolAddress((void**)&rx, g_rx);
    cudaGetSymbolAddress((void**)&c0, g_c0);
    cudaGetSymbolAddress((void**)&c0q, g_c0q);
    cudaGetSymbolAddress((void**)&s1base, g_s1);
    cudaGetSymbolAddress((void**)&s2base, g_s2);
    cudaGetSymbolAddress((void**)&s3base, g_s3);
    cudaGetSymbolAddress((void**)&fw0T, g_fw0T);
    cudaGetSymbolAddress((void**)&fw1T, g_fw1T);
    cudaGetSymbolAddress((void**)&bw1T, g_bw1T);

    __half* s1p[2] = { s1base, s1base + (size_t)BSZ * HID };
    __half* s2p[2] = { s2base, s2base + (size_t)BSZ * HID };
    float*  s3p[2] = { s3base, s3base + (size_t)BSZ * NOUT };

    {
        dim3 blk(32, 8);
        transpose64_kernel<<<dim3(HID / 64, NIN / 64), blk>>>(fw0, fw0T, NIN, HID);
        transpose64_kernel<<<dim3(HID / 64, HID / 64), blk>>>(fw1, fw1T, HID, HID);
        transpose64_kernel<<<dim3(HID / 64, HID / 64), blk>>>(bw1, bw1T, HID, HID);
    }

    clip_kernel<<<(BSZ * NIN + 255) / 256, 256>>>(x, rx, BSZ * NIN);

    // c0 = rx @ fw0 (loop-invariant), fp32 output
    c0_kernel<<<64, NTHREADS, SMEM_BYTES>>>(rx, fw0T, c0);

    // step 0 collapses to elementwise (states start at zero)
    init_kernel<<<(BSZ * HID + 255) / 256, 256>>>(c0, c0q, s1p[1], s2p[1], s3p[1]);

    // steps 1..23 write fp16 state buffers
    for (int t = 1; t < STEPS_TOTAL - 1; t++) {
        const int p = t & 1;
        const int q = 1 - p;
        const int weak = (t >= STEPS_FREE) ? 1 : 0;
        step_kernel<false><<<136, NTHREADS, SMEM_BYTES>>>(
            s1p[p], s2p[p], s3p[p],
            s1p[q], s2p[q], s3p[q],
            fw1T, bw1T, bw2, fw2, c0q, y, nullptr, weak);
    }

    // final step (t = 24) writes fp32 results directly into d_out
    {
        const int t = STEPS_TOTAL - 1;   // 24
        const int p = t & 1;             // 0
        const int q = 1 - p;
        step_kernel<true><<<136, NTHREADS, SMEM_BYTES>>>(
            s1p[p], s2p[p], s3p[p],
            s1p[q], s2p[q], s3p[q],
            fw1T, bw1T, bw2, fw2, c0q, y, out, 1);
    }
}

// round 15
// speedup vs baseline: 1.1475x; 1.1475x over previous
#include <cuda_runtime.h>
#include <cuda_fp16.h>
#include <cstdint>

#define BSZ 256
#define HID 4096
#define NIN 1024
#define NOUT 10
#define STEPS_TOTAL 25
#define STEPS_FREE 20
#define OUTW (2 * HID + NOUT)   // 8202
#define NTHREADS 512

// GEMM tiling: BM=BN=128, BK=64 halfs per iter, 512 threads (16 warps, warp tile 32x32)
#define BKK 64
#define NSTAGE 4
#define ROWH 72                            // smem row stride in halfs (144 B)
#define STAGE_HALFS (2 * 128 * ROWH)       // A + B tiles
#define STAGE_BYTES (STAGE_HALFS * 2)      // 36864
// smem: 128 B mbarrier header + stages
#define SMEM_BYTES (128 + NSTAGE * STAGE_BYTES)

// ---------------- persistent device scratch ----------------
__device__ __align__(128) __half g_rx[BSZ * NIN];
__device__ __align__(128) float  g_c0[BSZ * HID];
__device__ __align__(128) __half g_c0q[BSZ * HID];      // 0.25*c0, fp16
__device__ __align__(128) __half g_s1[2][BSZ * HID];
__device__ __align__(128) __half g_s2[2][BSZ * HID];
__device__ __align__(128) float  g_s3[2][BSZ * NOUT];
__device__ __align__(128) __half g_fw0T[(size_t)HID * NIN];
__device__ __align__(128) __half g_fw1T[(size_t)HID * HID];
__device__ __align__(128) __half g_bw1T[(size_t)HID * HID];

// ---------------- helpers ----------------
__device__ __forceinline__ uint32_t smem_u32(const void* p) {
    uint32_t a;
    asm("{ .reg .u64 t; cvta.to.shared.u64 t, %1; cvt.u32.u64 %0, t; }"
        : "=r"(a) : "l"(p));
    return a;
}

__device__ __forceinline__ void mbar_init(uint32_t addr, uint32_t cnt) {
    asm volatile("mbarrier.init.shared.b64 [%0], %1;" :: "r"(addr), "r"(cnt) : "memory");
}

// acquire-parity wait (proven compilable in R2)
__device__ __forceinline__ void mbar_wait(uint32_t addr, uint32_t parity) {
    asm volatile(
        "{\n\t.reg .pred P;\n"
        "W%=:\n\t"
        "mbarrier.try_wait.parity.acquire.cta.shared::cta.b64 P, [%0], %1, 0x989680;\n\t"
        "@P bra D%=;\n\t"
        "bra W%=;\n"
        "D%=:\n\t}"
        :: "r"(addr), "r"(parity) : "memory");
}

__device__ __forceinline__ void bulk_ldg(uint32_t dst, const void* src,
                                         uint32_t bytes, uint32_t mbar) {
    asm volatile(
        "cp.async.bulk.shared::cluster.global.mbarrier::complete_tx::bytes "
        "[%0], [%1], %2, [%3];"
        :: "r"(dst), "l"(src), "r"(bytes), "r"(mbar) : "memory");
}

__device__ __forceinline__ void mbar_expect(uint32_t addr, uint32_t bytes) {
    asm volatile("mbarrier.arrive.expect_tx.shared.b64 _, [%0], %1;"
                 :: "r"(addr), "r"(bytes) : "memory");
}

__device__ __forceinline__ void ldsm4(uint32_t& r0, uint32_t& r1,
                                      uint32_t& r2, uint32_t& r3, uint32_t addr) {
    asm volatile("ldmatrix.sync.aligned.m8n8.x4.shared.b16 {%0,%1,%2,%3}, [%4];"
                 : "=r"(r0), "=r"(r1), "=r"(r2), "=r"(r3) : "r"(addr));
}

// m16n8k16 fp16 mma, fp32 accum
__device__ __forceinline__ void mma_f16(float* c, const uint32_t* a,
                                        uint32_t b0, uint32_t b1) {
    asm volatile(
        "mma.sync.aligned.m16n8k16.row.col.f32.f16.f16.f32 "
        "{%0,%1,%2,%3}, {%4,%5,%6,%7}, {%8,%9}, {%0,%1,%2,%3};"
        : "+f"(c[0]), "+f"(c[1]), "+f"(c[2]), "+f"(c[3])
        : "r"(a[0]), "r"(a[1]), "r"(a[2]), "r"(a[3]), "r"(b0), "r"(b1));
}

// ---------------- GEMM tile (device) ----------------
// [128,128] tile at (rowBase,colBase) of D[M,4096] = A[M,K] @ BT[4096,K]^T
// 16 warps: warpM = wid&3 (rows), warpN = wid>>2 (cols); warp tile 32x32.
// Loads via cp.async.bulk (128 B per tile row) + mbarrier per stage.
// MODE 0: OutF = acc (fp32)                                   (c0)
// MODE 1: v = clip(0.5*Sold + C0q + 0.25*acc)                 (s1; C0q = 0.25*c0)
// MODE 2: v = clip(0.5*Sold + 0.25*(acc + s3old@bw2))         (s2)
// FINAL=false: OutH = h(v);  FINAL=true: fOut[row*OUTW + fColOff + col] = v (fp32)
template <int MODE, bool FINAL>
__device__ __forceinline__ void gemm_tile(
    const __half* __restrict__ A, const __half* __restrict__ BT, int K,
    float* __restrict__ OutF, __half* __restrict__ OutH,
    const __half* __restrict__ Sold, const __half* __restrict__ C0q,
    const float* __restrict__ s3old, const float* __restrict__ bw2,
    float* __restrict__ fOut, int fColOff,
    int rowBase, int colBase, __half* smem)
{
    const int tid  = threadIdx.x;
    const int lane = tid & 31;
    const int wid  = tid >> 5;              // 0..15
    const int g = lane >> 2, q = lane & 3;
    const int warpM = wid & 3;              // 4 row-groups of 32
    const int warpN = wid >> 2;             // 4 col-groups of 32

    const uint32_t mbar0 = smem_u32(smem);  // 4 mbarriers at smem[0..32)
    __half* stg = smem + 64;                // stages start at +128 B

    float acc[2][4][4];
#pragma unroll
    for (int mi = 0; mi < 2; mi++)
#pragma unroll
        for (int ni = 0; ni < 4; ni++)
#pragma unroll
            for (int t = 0; t < 4; t++) acc[mi][ni][t] = 0.0f;

    // producer setup: threads 0..255 each own one tile row (A for 0..127, B for 128..255)
    const int prow = tid & 127;
    const bool isA = tid < 128;
    const __half* gsrc = isA ? (A + (size_t)(rowBase + prow) * K)
                             : (BT + (size_t)(colBase + prow) * K);
    const uint32_t sdst0 = smem_u32(stg + prow * ROWH + (isA ? 0 : 128 * ROWH));

    const int nIt = K / BKK;

#define ISSUE_STAGE(s, kt)                                            \
    do {                                                              \
        if (tid < 256) {                                              \
            const uint32_t mb = mbar0 + (s) * 8;                      \
            mbar_expect(mb, 128u);                                    \
            bulk_ldg(sdst0 + (s) * (uint32_t)STAGE_BYTES,             \
                     gsrc + (kt), 128u, mb);                          \
        }                                                             \
    } while (0)

    // init mbarriers (256 arrivals = 256 producer arrive.expect_tx per stage)
    if (tid == 0) {
#pragma unroll
        for (int s = 0; s < NSTAGE; s++) mbar_init(mbar0 + s * 8, 256u);
    }
    __syncthreads();

    ISSUE_STAGE(0, 0);
    ISSUE_STAGE(1, BKK);
    ISSUE_STAGE(2, 2 * BKK);

    const int lrow = (lane & 7) + ((lane >> 3) & 1) * 8;
    const int lcolB = ((lane >> 4) & 1) * 16;   // bytes

    uint32_t a[2][2][4];   // [buf][mi][frag]
    uint32_t b[2][2][4];   // [buf][nj][frag]

#define LOAD_FRAGS(buf, aB, bB, ko)                                          \
    do {                                                                     \
        _Pragma("unroll")                                                    \
        for (int mi = 0; mi < 2; mi++)                                       \
            ldsm4(a[buf][mi][0], a[buf][mi][1], a[buf][mi][2], a[buf][mi][3],\
                  (aB) + mi * 16 * (ROWH * 2) + (ko));                       \
        _Pragma("unroll")                                                    \
        for (int nj = 0; nj < 2; nj++)                                       \
            ldsm4(b[buf][nj][0], b[buf][nj][1], b[buf][nj][2], b[buf][nj][3],\
                  (bB) + nj * 16 * (ROWH * 2) + (ko));                       \
    } while (0)

#define DO_MMA(buf)                                                          \
    do {                                                                     \
        _Pragma("unroll")                                                    \
        for (int nj = 0; nj < 2; nj++) {                                     \
            mma_f16(acc[0][nj * 2 + 0], a[buf][0], b[buf][nj][0], b[buf][nj][2]); \
            mma_f16(acc[0][nj * 2 + 1], a[buf][0], b[buf][nj][1], b[buf][nj][3]); \
            mma_f16(acc[1][nj * 2 + 0], a[buf][1], b[buf][nj][0], b[buf][nj][2]); \
            mma_f16(acc[1][nj * 2 + 1], a[buf][1], b[buf][nj][1], b[buf][nj][3]); \
        }                                                                    \
    } while (0)

    // prime: wait for stage 0 data, then load its first k-step fragments
    mbar_wait(mbar0 + 0, 0u);
    __syncthreads();
    {
        const __half* As = stg;
        const __half* Bs = As + 128 * ROWH;
        const uint32_t aB = smem_u32(As + (warpM * 32 + lrow) * ROWH) + lcolB;
        const uint32_t bB = smem_u32(Bs + (warpN * 32 + lrow) * ROWH) + lcolB;
        LOAD_FRAGS(0, aB, bB, 0);
    }

    for (int it = 0; it < nIt; ++it) {
        // issue loads for stage it+3 (buffer (it-1)&3; all reads of it-1 done
        // before the previous boundary's __syncthreads)
        if (it + 3 < nIt) {
            ISSUE_STAGE((it + 3) & (NSTAGE - 1), (it + 3) * BKK);
        }

        const __half* As = stg + (it & (NSTAGE - 1)) * STAGE_HALFS;
        const __half* Bs = As + 128 * ROWH;
        const uint32_t aB = smem_u32(As + (warpM * 32 + lrow) * ROWH) + lcolB;
        const uint32_t bB = smem_u32(Bs + (warpN * 32 + lrow) * ROWH) + lcolB;

        // k-steps 0..2: prefetch ks+1 into other buffer, then mma current
#pragma unroll
        for (int ks = 0; ks < 3; ks++) {
            LOAD_FRAGS((ks + 1) & 1, aB, bB, (ks + 1) * 32);
            DO_MMA(ks & 1);
        }

        // boundary: wait next stage's data, prefetch its first k-step
        if (it + 1 < nIt) {
            mbar_wait(mbar0 + ((it + 1) & (NSTAGE - 1)) * 8,
                      ((uint32_t)(it + 1) >> 2) & 1u);
            __syncthreads();
            const __half* As2 = stg + ((it + 1) & (NSTAGE - 1)) * STAGE_HALFS;
            const __half* Bs2 = As2 + 128 * ROWH;
            const uint32_t aB2 = smem_u32(As2 + (warpM * 32 + lrow) * ROWH) + lcolB;
            const uint32_t bB2 = smem_u32(Bs2 + (warpN * 32 + lrow) * ROWH) + lcolB;
            LOAD_FRAGS(0, aB2, bB2, 0);
        }
        DO_MMA(1);   // k-step 3 lives in buffer 1
    }
#undef LOAD_FRAGS
#undef DO_MMA
#undef ISSUE_STAGE

    // ---------------- epilogue ----------------
    const int rw = rowBase + warpM * 32;
    const int cw = colBase + warpN * 32;

    if (MODE == 2) {
        float s3r[2][2][10];
#pragma unroll
        for (int mi = 0; mi < 2; mi++)
#pragma unroll
            for (int h = 0; h < 2; h++) {
                const int r = rw + mi * 16 + h * 8 + g;
#pragma unroll
                for (int k = 0; k < NOUT; k++)
                    s3r[mi][h][k] = s3old[r * NOUT + k];
            }
#pragma unroll
        for (int ni = 0; ni < 4; ni++) {
            const int cb = cw + ni * 8 + q * 2;
#pragma unroll
            for (int k = 0; k < NOUT; k++) {
                const float2 b2 = *(const float2*)&bw2[(size_t)k * HID + cb];
#pragma unroll
                for (int mi = 0; mi < 2; mi++) {
                    acc[mi][ni][0] = fmaf(s3r[mi][0][k], b2.x, acc[mi][ni][0]);
                    acc[mi][ni][1] = fmaf(s3r[mi][0][k], b2.y, acc[mi][ni][1]);
                    acc[mi][ni][2] = fmaf(s3r[mi][1][k], b2.x, acc[mi][ni][2]);
                    acc[mi][ni][3] = fmaf(s3r[mi][1][k], b2.y, acc[mi][ni][3]);
                }
            }
        }
    }

#pragma unroll
    for (int mi = 0; mi < 2; mi++) {
#pragma unroll
        for (int ni = 0; ni < 4; ni++) {
            const int r0 = rw + mi * 16 + g;
            const int cb = cw + ni * 8 + q * 2;
#pragma unroll
            for (int h = 0; h < 2; h++) {
                const int row = r0 + h * 8;
                const size_t idx = (size_t)row * HID + cb;
                float vx = acc[mi][ni][h * 2 + 0];
                float vy = acc[mi][ni][h * 2 + 1];
                if (MODE == 0) {
                    *(float2*)&OutF[idx] = make_float2(vx, vy);
                } else {
                    const float2 so = __half22float2(*(const __half2*)&Sold[idx]);
                    if (MODE == 1) {
                        const float2 c2 = __half22float2(*(const __half2*)&C0q[idx]);
                        vx = 0.5f * so.x + c2.x + 0.25f * vx;
                        vy = 0.5f * so.y + c2.y + 0.25f * vy;
                    } else {
                        vx = 0.5f * so.x + 0.25f * vx;
                        vy = 0.5f * so.y + 0.25f * vy;
                    }
                    vx = fminf(fmaxf(vx, 0.0f), 1.0f);
                    vy = fminf(fmaxf(vy, 0.0f), 1.0f);
                    if (FINAL) {
                        *(float2*)&fOut[(size_t)row * OUTW + fColOff + cb] =
                            make_float2(vx, vy);
                    } else {
                        *(__half2*)&OutH[idx] = __floats2half2_rn(vx, vy);
                    }
                }
            }
        }
    }
}

// ---------------- s3 tile (device): 32 rows, 512 threads ----------------
template <bool FINAL>
__device__ __forceinline__ void s3_tile(
    const __half* __restrict__ s2old, const float* __restrict__ fw2,
    const float* __restrict__ s3old, const float* __restrict__ y,
    float* __restrict__ s3new, float* __restrict__ fOut,
    int weak, int rowBase, __half* smem_raw)
{
    const int tid = threadIdx.x, lane = tid & 31, wid = tid >> 5;   // 16 warps
    float* fs = (float*)smem_raw;
    float acc[2][NOUT];
#pragma unroll
    for (int r = 0; r < 2; r++)
#pragma unroll
        for (int j = 0; j < NOUT; j++) acc[r][j] = 0.0f;

    for (int c = 0; c < 8; c++) {
        __syncthreads();
        for (int i = tid; i < 512 * NOUT; i += NTHREADS) {
            int kl = i / NOUT, j = i - kl * NOUT;
            fs[kl * 11 + j] = fw2[(size_t)(c * 512 + kl) * NOUT + j];
        }
        __syncthreads();
#pragma unroll
        for (int r = 0; r < 2; r++) {
            const int row = rowBase + wid * 2 + r;
            const __half* s2r = s2old + (size_t)row * HID + c * 512;
#pragma unroll 4
            for (int i = 0; i < 16; i++) {
                const int kl = lane + i * 32;
                const float sv = __half2float(s2r[kl]);
#pragma unroll
                for (int j = 0; j < NOUT; j++)
                    acc[r][j] = fmaf(sv, fs[kl * 11 + j], acc[r][j]);
            }
        }
    }

#pragma unroll
    for (int r = 0; r < 2; r++) {
        const int row = rowBase + wid * 2 + r;
#pragma unroll
        for (int j = 0; j < NOUT; j++) {
            float v = acc[r][j];
#pragma unroll
            for (int o = 16; o; o >>= 1) v += __shfl_xor_sync(0xffffffffu, v, o);
            if (lane == 0) {
                float out = weak ? 0.5f * (v + y[row * NOUT + j])
                                 : 0.5f * (s3old[row * NOUT + j] + v);
                out = fminf(fmaxf(out, 0.0f), 1.0f);
                if (FINAL) fOut[(size_t)row * OUTW + 2 * HID + j] = out;
                else       s3new[row * NOUT + j] = out;
            }
        }
    }
}

// ---------------- fused step kernel: 136 CTAs = one wave ----------------
template <bool FINAL>
__global__ __launch_bounds__(NTHREADS, 1) void step_kernel(
    const __half* __restrict__ s1old, const __half* __restrict__ s2old,
    const float* __restrict__ s3old,
    __half* __restrict__ s1new, __half* __restrict__ s2new, float* __restrict__ s3new,
    const __half* __restrict__ fw1T, const __half* __restrict__ bw1T,
    const float* __restrict__ bw2, const float* __restrict__ fw2,
    const __half* __restrict__ c0q, const float* __restrict__ y,
    float* __restrict__ fOut, int weak)
{
    extern __shared__ __half smem[];
    const int bid = blockIdx.x;
    if (bid < 64) {
        gemm_tile<1, FINAL>(s2old, bw1T, HID, nullptr, s1new, s1old, c0q, nullptr,
                            nullptr, fOut, 0,
                            (bid >> 5) * 128, (bid & 31) * 128, smem);
    } else if (bid < 128) {
        const int t = bid - 64;
        gemm_tile<2, FINAL>(s1old, fw1T, HID, nullptr, s2new, s2old, nullptr, s3old,
                            bw2, fOut, HID,
                            (t >> 5) * 128, (t & 31) * 128, smem);
    } else {
        s3_tile<FINAL>(s2old, fw2, s3old, y, s3new, fOut, weak, (bid - 128) * 32, smem);
    }
}

__global__ __launch_bounds__(NTHREADS, 1) void c0_kernel(
    const __half* __restrict__ rx, const __half* __restrict__ fw0T,
    float* __restrict__ c0)
{
    extern __shared__ __half smem[];
    const int bid = blockIdx.x;
    gemm_tile<0, false>(rx, fw0T, NIN, c0, nullptr, nullptr, nullptr, nullptr,
                        nullptr, nullptr, 0,
                        (bid >> 5) * 128, (bid & 31) * 128, smem);
}

// ---------------- small kernels ----------------
__global__ void clip_kernel(const float* __restrict__ x, __half* __restrict__ rx, int n) {
    int i = blockIdx.x * blockDim.x + threadIdx.x;
    if (i < n) rx[i] = __float2half_rn(fminf(fmaxf(x[i], 0.0f), 1.0f));
}

__global__ void init_kernel(const float* __restrict__ c0, __half* __restrict__ c0q,
                            __half* __restrict__ s1, __half* __restrict__ s2,
                            float* __restrict__ s3) {
    int i = blockIdx.x * blockDim.x + threadIdx.x;
    if (i < BSZ * HID) {
        float qc = 0.25f * c0[i];
        c0q[i] = __float2half_rn(qc);
        s1[i] = __float2half_rn(fminf(fmaxf(qc, 0.0f), 1.0f));
        s2[i] = __half(0.0f);
    }
    if (i < BSZ * NOUT) s3[i] = 0.0f;
}

// 64x64-tile transpose+convert: dst[c][r] = h(src[r][c]); full-width fp16 stores.
__global__ void transpose64_kernel(const float* __restrict__ src,
                                   __half* __restrict__ dst, int R, int C) {
    __shared__ float tile[64][65];
    const int bx = blockIdx.x * 64;
    const int by = blockIdx.y * 64;
    const int tx = threadIdx.x, ty = threadIdx.y;
#pragma unroll
    for (int j = 0; j < 2; j++)
#pragma unroll
        for (int i = 0; i < 8; i++)
            tile[ty + i * 8][tx + j * 32] =
                src[(size_t)(by + ty + i * 8) * C + bx + tx + j * 32];
    __syncthreads();
#pragma unroll
    for (int i = 0; i < 8; i++) {
        const int cc = bx + ty + i * 8;
        const int k = ty + i * 8;
        __half2 v = __floats2half2_rn(tile[tx * 2][k], tile[tx * 2 + 1][k]);
        *(__half2*)&dst[(size_t)cc * R + by + tx * 2] = v;
    }
}

// ---------------- launch ----------------
extern "C" void kernel_launch(void* const* d_in, const int* in_sizes, int n_in,
                              void* d_out, int out_size)
{
    const float* x   = (const float*)d_in[0];
    const float* fw0 = (const float*)d_in[1];
    const float* fw1 = (const float*)d_in[2];
    const float* fw2 = (const float*)d_in[3];
    // d_in[4] = bw0 (unused by the dynamics)
    const float* bw1 = (const float*)d_in[5];
    const float* bw2 = (const float*)d_in[6];
    const float* y   = (const float*)d_in[7];
    float* out = (float*)d_out;

    cudaFuncSetAttribute(step_kernel<false>, cudaFuncAttributeMaxDynamicSharedMemorySize, SMEM_BYTES);
    cudaFuncSetAttribute(step_kernel<true>,  cudaFuncAttributeMaxDynamicSharedMemorySize, SMEM_BYTES);
    cudaFuncSetAttribute(c0_kernel,          cudaFuncAttributeMaxDynamicSharedMemorySize, SMEM_BYTES);

    __half *rx, *c0q, *s1base, *s2base, *fw0T, *fw1T, *bw1T;
    float *c0, *s3base;
    cudaGetSymbolAddress((void**)&rx, g_rx);
    cudaGetSymbolAddress((void**)&c0, g_c0);
    cudaGetSymbolAddress((void**)&c0q, g_c0q);
    cudaGetSymbolAddress((void**)&s1base, g_s1);
    cudaGetSymbolAddress((void**)&s2base, g_s2);
    cudaGetSymbolAddress((void**)&s3base, g_s3);
    cudaGetSymbolAddress((void**)&fw0T, g_fw0T);
    cudaGetSymbolAddress((void**)&fw1T, g_fw1T);
    cudaGetSymbolAddress((void**)&bw1T, g_bw1T);

    __half* s1p[2] = { s1base, s1base + (size_t)BSZ * HID };
    __half* s2p[2] = { s2base, s2base + (size_t)BSZ * HID };
    float*  s3p[2] = { s3base, s3base + (size_t)BSZ * NOUT };

    {
        dim3 blk(32, 8);
        transpose64_kernel<<<dim3(HID / 64, NIN / 64), blk>>>(fw0, fw0T, NIN, HID);
        transpose64_kernel<<<dim3(HID / 64, HID / 64), blk>>>(fw1, fw1T, HID, HID);
        transpose64_kernel<<<dim3(HID / 64, HID / 64), blk>>>(bw1, bw1T, HID, HID);
    }

    clip_kernel<<<(BSZ * NIN + 255) / 256, 256>>>(x, rx, BSZ * NIN);

    // c0 = rx @ fw0 (loop-invariant), fp32 output
    c0_kernel<<<64, NTHREADS, SMEM_BYTES>>>(rx, fw0T, c0);

    // step 0 collapses to elementwise (states start at zero)
    init_kernel<<<(BSZ * HID + 255) / 256, 256>>>(c0, c0q, s1p[1], s2p[1], s3p[1]);

    // steps 1..23 write fp16 state buffers
    for (int t = 1; t < STEPS_TOTAL - 1; t++) {
        const int p = t & 1;
        const int q = 1 - p;
        const int weak = (t >= STEPS_FREE) ? 1 : 0;
        step_kernel<false><<<136, NTHREADS, SMEM_BYTES>>>(
            s1p[p], s2p[p], s3p[p],
            s1p[q], s2p[q], s3p[q],
            fw1T, bw1T, bw2, fw2, c0q, y, nullptr, weak);
    }

    // final step (t = 24) writes fp32 results directly into d_out
    {
        const int t = STEPS_TOTAL - 1;   // 24
        const int p = t & 1;             // 0
        const int q = 1 - p;
        step_kernel<true><<<136, NTHREADS, SMEM_BYTES>>>(
            s1p[p], s2p[p], s3p[p],
            s1p[q], s2p[q], s3p[q],
            fw1T, bw1T, bw2, fw2, c0q, y, out, 1);
    }
}

// round 16
// speedup vs baseline: 1.5823x; 1.3790x over previous
#include <cuda_runtime.h>
#include <cuda_fp16.h>
#include <cstdint>

#define BSZ 256
#define HID 4096
#define NIN 1024
#define NOUT 10
#define STEPS_TOTAL 25
#define STEPS_FREE 20
#define OUTW (2 * HID + NOUT)   // 8202
#define NTHREADS 512

// GEMM tiling: BM=BN=128, BK=64 halfs per iter, 512 threads (16 warps, warp tile 32x32)
#define BKK 64
#define NSTAGE 4
#define ROWH 72                            // smem row stride in halfs (144 B)
#define STAGE_HALFS (2 * 128 * ROWH)       // A + B tiles
#define SMEM_BYTES (NSTAGE * STAGE_HALFS * 2)  // 147456 B

// ---------------- persistent device scratch ----------------
__device__ __align__(128) __half g_rx[BSZ * NIN];
__device__ __align__(128) float  g_c0[BSZ * HID];
__device__ __align__(128) __half g_c0q[BSZ * HID];      // 0.25*c0, fp16
__device__ __align__(128) __half g_s1[2][BSZ * HID];
__device__ __align__(128) __half g_s2[2][BSZ * HID];
__device__ __align__(128) float  g_s3[2][BSZ * NOUT];
__device__ __align__(128) __half g_fw0T[(size_t)HID * NIN];
__device__ __align__(128) __half g_fw1T[(size_t)HID * HID];
__device__ __align__(128) __half g_bw1T[(size_t)HID * HID];

// ---------------- helpers ----------------
__device__ __forceinline__ uint32_t smem_u32(const void* p) {
    uint32_t a;
    asm("{ .reg .u64 t; cvta.to.shared.u64 t, %1; cvt.u32.u64 %0, t; }"
        : "=r"(a) : "l"(p));
    return a;
}

__device__ __forceinline__ void cp16(uint32_t dst, const void* src) {
    asm volatile("cp.async.cg.shared.global [%0], [%1], 16;"
                 :: "r"(dst), "l"(src) : "memory");
}
#define CP_COMMIT() asm volatile("cp.async.commit_group;" ::: "memory")
#define CP_WAIT(n)  asm volatile("cp.async.wait_group %0;" :: "n"(n) : "memory")

__device__ __forceinline__ void ldsm4(uint32_t& r0, uint32_t& r1,
                                      uint32_t& r2, uint32_t& r3, uint32_t addr) {
    asm volatile("ldmatrix.sync.aligned.m8n8.x4.shared.b16 {%0,%1,%2,%3}, [%4];"
                 : "=r"(r0), "=r"(r1), "=r"(r2), "=r"(r3) : "r"(addr));
}

// m16n8k16 fp16 mma, fp32 accum
__device__ __forceinline__ void mma_f16(float* c, const uint32_t* a,
                                        uint32_t b0, uint32_t b1) {
    asm volatile(
        "mma.sync.aligned.m16n8k16.row.col.f32.f16.f16.f32 "
        "{%0,%1,%2,%3}, {%4,%5,%6,%7}, {%8,%9}, {%0,%1,%2,%3};"
        : "+f"(c[0]), "+f"(c[1]), "+f"(c[2]), "+f"(c[3])
        : "r"(a[0]), "r"(a[1]), "r"(a[2]), "r"(a[3]), "r"(b0), "r"(b1));
}

// ---------------- GEMM tile (device) ----------------
// [128,128] tile at (rowBase,colBase) of D[M,4096] = A[M,K] @ BT[4096,K]^T
// 16 warps: warpM = wid&3 (rows), warpN = wid>>2 (cols); warp tile 32x32.
// Pair-wise pipeline: 2 stages consumed per CP_WAIT/__syncthreads boundary.
// MODE 0: OutF = acc (fp32)                                   (c0)
// MODE 1: v = clip(0.5*Sold + C0q + 0.25*acc)                 (s1; C0q = 0.25*c0)
// MODE 2: v = clip(0.5*Sold + 0.25*(acc + s3old@bw2))         (s2)
// FINAL=false: OutH = h(v);  FINAL=true: fOut[row*OUTW + fColOff + col] = v (fp32)
template <int MODE, bool FINAL>
__device__ __forceinline__ void gemm_tile(
    const __half* __restrict__ A, const __half* __restrict__ BT, int K,
    float* __restrict__ OutF, __half* __restrict__ OutH,
    const __half* __restrict__ Sold, const __half* __restrict__ C0q,
    const float* __restrict__ s3old, const float* __restrict__ bw2,
    float* __restrict__ fOut, int fColOff,
    int rowBase, int colBase, __half* smem)
{
    const int tid  = threadIdx.x;
    const int lane = tid & 31;
    const int wid  = tid >> 5;              // 0..15
    const int g = lane >> 2, q = lane & 3;
    const int warpM = wid & 3;              // 4 row-groups of 32
    const int warpN = wid >> 2;             // 4 col-groups of 32

    float acc[2][4][4];
#pragma unroll
    for (int mi = 0; mi < 2; mi++)
#pragma unroll
        for (int ni = 0; ni < 4; ni++)
#pragma unroll
            for (int t = 0; t < 4; t++) acc[mi][ni][t] = 0.0f;

    // loaders: 512 threads, row = tid>>2, 2 of 8 16B-segments each for A and B
    const int ldr  = tid >> 2;              // 0..127
    const int seg0 = (tid & 3) * 2;         // 0,2,4,6

    const __half* Ag = A  + (size_t)(rowBase + ldr) * K;
    const __half* Bg = BT + (size_t)(colBase + ldr) * K;

    const int nIt = K / BKK;                // 64 or 16 (even)

#define LOAD_STAGE(s, kt)                                            \
    do {                                                             \
        __half* As_ = smem + (s) * STAGE_HALFS;                      \
        __half* Bs_ = As_ + 128 * ROWH;                              \
        uint32_t dA = smem_u32(As_ + ldr * ROWH);                    \
        uint32_t dB = smem_u32(Bs_ + ldr * ROWH);                    \
        _Pragma("unroll")                                            \
        for (int u = 0; u < 2; u++) {                                \
            int sg = seg0 + u;                                       \
            cp16(dA + sg * 16, Ag + (kt) + sg * 8);                  \
            cp16(dB + sg * 16, Bg + (kt) + sg * 8);                  \
        }                                                            \
    } while (0)

    const int lrow = (lane & 7) + ((lane >> 3) & 1) * 8;
    const int lcolB = ((lane >> 4) & 1) * 16;   // bytes

    uint32_t a[2][2][4];   // [buf][mi][frag]
    uint32_t b[2][2][4];   // [buf][nj][frag]

#define LOAD_FRAGS(buf, aB, bB, ko)                                          \
    do {                                                                     \
        _Pragma("unroll")                                                    \
        for (int mi = 0; mi < 2; mi++)                                       \
            ldsm4(a[buf][mi][0], a[buf][mi][1], a[buf][mi][2], a[buf][mi][3],\
                  (aB) + mi * 16 * (ROWH * 2) + (ko));                       \
        _Pragma("unroll")                                                    \
        for (int nj = 0; nj < 2; nj++)                                       \
            ldsm4(b[buf][nj][0], b[buf][nj][1], b[buf][nj][2], b[buf][nj][3],\
                  (bB) + nj * 16 * (ROWH * 2) + (ko));                       \
    } while (0)

#define DO_MMA(buf)                                                          \
    do {                                                                     \
        _Pragma("unroll")                                                    \
        for (int nj = 0; nj < 2; nj++) {                                     \
            mma_f16(acc[0][nj * 2 + 0], a[buf][0], b[buf][nj][0], b[buf][nj][2]); \
            mma_f16(acc[0][nj * 2 + 1], a[buf][0], b[buf][nj][1], b[buf][nj][3]); \
            mma_f16(acc[1][nj * 2 + 0], a[buf][1], b[buf][nj][0], b[buf][nj][2]); \
            mma_f16(acc[1][nj * 2 + 1], a[buf][1], b[buf][nj][1], b[buf][nj][3]); \
        }                                                                    \
    } while (0)

#define STAGE_BASES(s, aB, bB)                                               \
    const __half* As_##aB = smem + (s) * STAGE_HALFS;                        \
    const uint32_t aB = smem_u32(As_##aB + (warpM * 32 + lrow) * ROWH) + lcolB; \
    const uint32_t bB = smem_u32(As_##aB + 128 * ROWH + (warpN * 32 + lrow) * ROWH) + lcolB;

    // prime: load stages 0,1; wait; prefetch stage0 k-step 0
    LOAD_STAGE(0, 0);   CP_COMMIT();
    LOAD_STAGE(1, BKK); CP_COMMIT();
    CP_WAIT(0);
    __syncthreads();
    {
        STAGE_BASES(0, aB0, bB0);
        LOAD_FRAGS(0, aB0, bB0, 0);
    }

    for (int it = 0; it < nIt; it += 2) {
        // issue next pair of stages (overwrite buffers of it-2, it-1; safe after entry sync)
        if (it + 2 < nIt) { LOAD_STAGE((it + 2) & 3, (it + 2) * BKK); CP_COMMIT(); }
        if (it + 3 < nIt) { LOAD_STAGE((it + 3) & 3, (it + 3) * BKK); CP_COMMIT(); }

        STAGE_BASES((it) & 3, aBA, bBA);
        STAGE_BASES((it + 1) & 3, aBB, bBB);

        // ---- stage it: k-steps 0..3 (frag double-buffer) ----
#pragma unroll
        for (int ks = 0; ks < 3; ks++) {
            LOAD_FRAGS((ks + 1) & 1, aBA, bBA, (ks + 1) * 32);
            DO_MMA(ks & 1);
        }
        LOAD_FRAGS(0, aBB, bBB, 0);   // stage it+1 ks0 (data ready since entry)
        DO_MMA(1);

        // ---- stage it+1: k-steps 0..3 ----
#pragma unroll
        for (int ks = 0; ks < 3; ks++) {
            LOAD_FRAGS((ks + 1) & 1, aBB, bBB, (ks + 1) * 32);
            DO_MMA(ks & 1);
        }
        // pair boundary: wait for the 2 stages issued this pair, prefetch next
        if (it + 2 < nIt) {
            CP_WAIT(0);
            __syncthreads();
            STAGE_BASES((it + 2) & 3, aBN, bBN);
            LOAD_FRAGS(0, aBN, bBN, 0);
        }
        DO_MMA(1);
    }
#undef STAGE_BASES
#undef LOAD_FRAGS
#undef DO_MMA
#undef LOAD_STAGE

    // ---------------- epilogue ----------------
    const int rw = rowBase + warpM * 32;
    const int cw = colBase + warpN * 32;

    if (MODE == 2) {
        float s3r[2][2][10];
#pragma unroll
        for (int mi = 0; mi < 2; mi++)
#pragma unroll
            for (int h = 0; h < 2; h++) {
                const int r = rw + mi * 16 + h * 8 + g;
#pragma unroll
                for (int k = 0; k < NOUT; k++)
                    s3r[mi][h][k] = s3old[r * NOUT + k];
            }
#pragma unroll
        for (int ni = 0; ni < 4; ni++) {
            const int cb = cw + ni * 8 + q * 2;
#pragma unroll
            for (int k = 0; k < NOUT; k++) {
                const float2 b2 = *(const float2*)&bw2[(size_t)k * HID + cb];
#pragma unroll
                for (int mi = 0; mi < 2; mi++) {
                    acc[mi][ni][0] = fmaf(s3r[mi][0][k], b2.x, acc[mi][ni][0]);
                    acc[mi][ni][1] = fmaf(s3r[mi][0][k], b2.y, acc[mi][ni][1]);
                    acc[mi][ni][2] = fmaf(s3r[mi][1][k], b2.x, acc[mi][ni][2]);
                    acc[mi][ni][3] = fmaf(s3r[mi][1][k], b2.y, acc[mi][ni][3]);
                }
            }
        }
    }

#pragma unroll
    for (int mi = 0; mi < 2; mi++) {
#pragma unroll
        for (int ni = 0; ni < 4; ni++) {
            const int r0 = rw + mi * 16 + g;
            const int cb = cw + ni * 8 + q * 2;
#pragma unroll
            for (int h = 0; h < 2; h++) {
                const int row = r0 + h * 8;
                const size_t idx = (size_t)row * HID + cb;
                float vx = acc[mi][ni][h * 2 + 0];
                float vy = acc[mi][ni][h * 2 + 1];
                if (MODE == 0) {
                    *(float2*)&OutF[idx] = make_float2(vx, vy);
                } else {
                    const float2 so = __half22float2(*(const __half2*)&Sold[idx]);
                    if (MODE == 1) {
                        const float2 c2 = __half22float2(*(const __half2*)&C0q[idx]);
                        vx = 0.5f * so.x + c2.x + 0.25f * vx;
                        vy = 0.5f * so.y + c2.y + 0.25f * vy;
                    } else {
                        vx = 0.5f * so.x + 0.25f * vx;
                        vy = 0.5f * so.y + 0.25f * vy;
                    }
                    vx = fminf(fmaxf(vx, 0.0f), 1.0f);
                    vy = fminf(fmaxf(vy, 0.0f), 1.0f);
                    if (FINAL) {
                        *(float2*)&fOut[(size_t)row * OUTW + fColOff + cb] =
                            make_float2(vx, vy);
                    } else {
                        *(__half2*)&OutH[idx] = __floats2half2_rn(vx, vy);
                    }
                }
            }
        }
    }
}

// ---------------- s3 tile (device): 32 rows, 512 threads ----------------
template <bool FINAL>
__device__ __forceinline__ void s3_tile(
    const __half* __restrict__ s2old, const float* __restrict__ fw2,
    const float* __restrict__ s3old, const float* __restrict__ y,
    float* __restrict__ s3new, float* __restrict__ fOut,
    int weak, int rowBase, __half* smem_raw)
{
    const int tid = threadIdx.x, lane = tid & 31, wid = tid >> 5;   // 16 warps
    float* fs = (float*)smem_raw;
    float acc[2][NOUT];
#pragma unroll
    for (int r = 0; r < 2; r++)
#pragma unroll
        for (int j = 0; j < NOUT; j++) acc[r][j] = 0.0f;

    for (int c = 0; c < 8; c++) {
        __syncthreads();
        for (int i = tid; i < 512 * NOUT; i += NTHREADS) {
            int kl = i / NOUT, j = i - kl * NOUT;
            fs[kl * 11 + j] = fw2[(size_t)(c * 512 + kl) * NOUT + j];
        }
        __syncthreads();
#pragma unroll
        for (int r = 0; r < 2; r++) {
            const int row = rowBase + wid * 2 + r;
            const __half* s2r = s2old + (size_t)row * HID + c * 512;
#pragma unroll 4
            for (int i = 0; i < 16; i++) {
                const int kl = lane + i * 32;
                const float sv = __half2float(s2r[kl]);
#pragma unroll
                for (int j = 0; j < NOUT; j++)
                    acc[r][j] = fmaf(sv, fs[kl * 11 + j], acc[r][j]);
            }
        }
    }

#pragma unroll
    for (int r = 0; r < 2; r++) {
        const int row = rowBase + wid * 2 + r;
#pragma unroll
        for (int j = 0; j < NOUT; j++) {
            float v = acc[r][j];
#pragma unroll
            for (int o = 16; o; o >>= 1) v += __shfl_xor_sync(0xffffffffu, v, o);
            if (lane == 0) {
                float out = weak ? 0.5f * (v + y[row * NOUT + j])
                                 : 0.5f * (s3old[row * NOUT + j] + v);
                out = fminf(fmaxf(out, 0.0f), 1.0f);
                if (FINAL) fOut[(size_t)row * OUTW + 2 * HID + j] = out;
                else       s3new[row * NOUT + j] = out;
            }
        }
    }
}

// ---------------- fused step kernel: 136 CTAs = one wave ----------------
template <bool FINAL>
__global__ __launch_bounds__(NTHREADS, 1) void step_kernel(
    const __half* __restrict__ s1old, const __half* __restrict__ s2old,
    const float* __restrict__ s3old,
    __half* __restrict__ s1new, __half* __restrict__ s2new, float* __restrict__ s3new,
    const __half* __restrict__ fw1T, const __half* __restrict__ bw1T,
    const float* __restrict__ bw2, const float* __restrict__ fw2,
    const __half* __restrict__ c0q, const float* __restrict__ y,
    float* __restrict__ fOut, int weak)
{
    extern __shared__ __half smem[];
    const int bid = blockIdx.x;
    if (bid < 64) {
        gemm_tile<1, FINAL>(s2old, bw1T, HID, nullptr, s1new, s1old, c0q, nullptr,
                            nullptr, fOut, 0,
                            (bid >> 5) * 128, (bid & 31) * 128, smem);
    } else if (bid < 128) {
        const int t = bid - 64;
        gemm_tile<2, FINAL>(s1old, fw1T, HID, nullptr, s2new, s2old, nullptr, s3old,
                            bw2, fOut, HID,
                            (t >> 5) * 128, (t & 31) * 128, smem);
    } else {
        s3_tile<FINAL>(s2old, fw2, s3old, y, s3new, fOut, weak, (bid - 128) * 32, smem);
    }
}

__global__ __launch_bounds__(NTHREADS, 1) void c0_kernel(
    const __half* __restrict__ rx, const __half* __restrict__ fw0T,
    float* __restrict__ c0)
{
    extern __shared__ __half smem[];
    const int bid = blockIdx.x;
    gemm_tile<0, false>(rx, fw0T, NIN, c0, nullptr, nullptr, nullptr, nullptr,
                        nullptr, nullptr, 0,
                        (bid >> 5) * 128, (bid & 31) * 128, smem);
}

// ---------------- small kernels ----------------
__global__ void clip_kernel(const float* __restrict__ x, __half* __restrict__ rx, int n) {
    int i = blockIdx.x * blockDim.x + threadIdx.x;
    if (i < n) rx[i] = __float2half_rn(fminf(fmaxf(x[i], 0.0f), 1.0f));
}

__global__ void init_kernel(const float* __restrict__ c0, __half* __restrict__ c0q,
                            __half* __restrict__ s1, __half* __restrict__ s2,
                            float* __restrict__ s3) {
    int i = blockIdx.x * blockDim.x + threadIdx.x;
    if (i < BSZ * HID) {
        float qc = 0.25f * c0[i];
        c0q[i] = __float2half_rn(qc);
        s1[i] = __float2half_rn(fminf(fmaxf(qc, 0.0f), 1.0f));
        s2[i] = __half(0.0f);
    }
    if (i < BSZ * NOUT) s3[i] = 0.0f;
}

// 64x64-tile transpose+convert: dst[c][r] = h(src[r][c]); full-width fp16 stores.
__global__ void transpose64_kernel(const float* __restrict__ src,
                                   __half* __restrict__ dst, int R, int C) {
    __shared__ float tile[64][65];
    const int bx = blockIdx.x * 64;
    const int by = blockIdx.y * 64;
    const int tx = threadIdx.x, ty = threadIdx.y;
#pragma unroll
    for (int j = 0; j < 2; j++)
#pragma unroll
        for (int i = 0; i < 8; i++)
            tile[ty + i * 8][tx + j * 32] =
                src[(size_t)(by + ty + i * 8) * C + bx + tx + j * 32];
    __syncthreads();
#pragma unroll
    for (int i = 0; i < 8; i++) {
        const int cc = bx + ty + i * 8;
        const int k = ty + i * 8;
        __half2 v = __floats2half2_rn(tile[tx * 2][k], tile[tx * 2 + 1][k]);
        *(__half2*)&dst[(size_t)cc * R + by + tx * 2] = v;
    }
}

// ---------------- launch ----------------
extern "C" void kernel_launch(void* const* d_in, const int* in_sizes, int n_in,
                              void* d_out, int out_size)
{
    const float* x   = (const float*)d_in[0];
    const float* fw0 = (const float*)d_in[1];
    const float* fw1 = (const float*)d_in[2];
    const float* fw2 = (const float*)d_in[3];
    // d_in[4] = bw0 (unused by the dynamics)
    const float* bw1 = (const float*)d_in[5];
    const float* bw2 = (const float*)d_in[6];
    const float* y   = (const float*)d_in[7];
    float* out = (float*)d_out;

    cudaFuncSetAttribute(step_kernel<false>, cudaFuncAttributeMaxDynamicSharedMemorySize, SMEM_BYTES);
    cudaFuncSetAttribute(step_kernel<true>,  cudaFuncAttributeMaxDynamicSharedMemorySize, SMEM_BYTES);
    cudaFuncSetAttribute(c0_kernel,          cudaFuncAttributeMaxDynamicSharedMemorySize, SMEM_BYTES);

    __half *rx, *c0q, *s1base, *s2base, *fw0T, *fw1T, *bw1T;
    float *c0, *s3base;
    cudaGetSymbolAddress((void**)&rx, g_rx);
    cudaGetSymbolAddress((void**)&c0, g_c0);
    cudaGetSymbolAddress((void**)&c0q, g_c0q);
    cudaGetSymbolAddress((void**)&s1base, g_s1);
    cudaGetSymbolAddress((void**)&s2base, g_s2);
    cudaGetSymbolAddress((void**)&s3base, g_s3);
    cudaGetSymbolAddress((void**)&fw0T, g_fw0T);
    cudaGetSymbolAddress((void**)&fw1T, g_fw1T);
    cudaGetSymbolAddress((void**)&bw1T, g_bw1T);

    __half* s1p[2] = { s1base, s1base + (size_t)BSZ * HID };
    __half* s2p[2] = { s2base, s2base + (size_t)BSZ * HID };
    float*  s3p[2] = { s3base, s3base + (size_t)BSZ * NOUT };

    {
        dim3 blk(32, 8);
        transpose64_kernel<<<dim3(HID / 64, NIN / 64), blk>>>(fw0, fw0T, NIN, HID);
        transpose64_kernel<<<dim3(HID / 64, HID / 64), blk>>>(fw1, fw1T, HID, HID);
        transpose64_kernel<<<dim3(HID / 64, HID / 64), blk>>>(bw1, bw1T, HID, HID);
    }

    clip_kernel<<<(BSZ * NIN + 255) / 256, 256>>>(x, rx, BSZ * NIN);

    // c0 = rx @ fw0 (loop-invariant), fp32 output
    c0_kernel<<<64, NTHREADS, SMEM_BYTES>>>(rx, fw0T, c0);

    // step 0 collapses to elementwise (states start at zero)
    init_kernel<<<(BSZ * HID + 255) / 256, 256>>>(c0, c0q, s1p[1], s2p[1], s3p[1]);

    // steps 1..23 write fp16 state buffers
    for (int t = 1; t < STEPS_TOTAL - 1; t++) {
        const int p = t & 1;
        const int q = 1 - p;
        const int weak = (t >= STEPS_FREE) ? 1 : 0;
        step_kernel<false><<<136, NTHREADS, SMEM_BYTES>>>(
            s1p[p], s2p[p], s3p[p],
            s1p[q], s2p[q], s3p[q],
            fw1T, bw1T, bw2, fw2, c0q, y, nullptr, weak);
    }

    // final step (t = 24) writes fp32 results directly into d_out
    {
        const int t = STEPS_TOTAL - 1;   // 24
        const int p = t & 1;             // 0
        const int q = 1 - p;
        step_kernel<true><<<136, NTHREADS, SMEM_BYTES>>>(
            s1p[p], s2p[p], s3p[p],
            s1p[q], s2p[q], s3p[q],
            fw1T, bw1T, bw2, fw2, c0q, y, out, 1);
    }
}

// round 17
// speedup vs baseline: 1.8631x; 1.1775x over previous
#include <cuda_runtime.h>
#include <cuda_fp16.h>
#include <cstdint>

#define BSZ 256
#define HID 4096
#define NIN 1024
#define NOUT 10
#define STEPS_TOTAL 25
#define STEPS_FREE 20
#define OUTW (2 * HID + NOUT)   // 8202
#define NTHREADS 512

// GEMM tiling: BM=BN=128, BK=64 halfs per iter, 512 threads (16 warps, warp tile 32x32)
#define BKK 64
#define NSTAGE 4
#define ROWH 72                            // smem row stride in halfs (144 B)
#define STAGE_HALFS (2 * 128 * ROWH)       // A + B tiles
#define SMEM_BYTES (NSTAGE * STAGE_HALFS * 2)  // 147456 B

// ---------------- persistent device scratch ----------------
__device__ __align__(128) __half g_rx[BSZ * NIN];
__device__ __align__(128) float  g_c0[BSZ * HID];
__device__ __align__(128) __half g_c0q[BSZ * HID];      // 0.25*c0, fp16
__device__ __align__(128) __half g_s1[2][BSZ * HID];
__device__ __align__(128) __half g_s2[2][BSZ * HID];
__device__ __align__(128) float  g_s3[2][BSZ * NOUT];
__device__ __align__(128) __half g_fw0T[(size_t)HID * NIN];
__device__ __align__(128) __half g_fw1T[(size_t)HID * HID];
__device__ __align__(128) __half g_bw1T[(size_t)HID * HID];

// ---------------- helpers ----------------
__device__ __forceinline__ uint32_t smem_u32(const void* p) {
    uint32_t a;
    asm("{ .reg .u64 t; cvta.to.shared.u64 t, %1; cvt.u32.u64 %0, t; }"
        : "=r"(a) : "l"(p));
    return a;
}

__device__ __forceinline__ void cp16(uint32_t dst, const void* src) {
    asm volatile("cp.async.cg.shared.global [%0], [%1], 16;"
                 :: "r"(dst), "l"(src) : "memory");
}
#define CP_COMMIT() asm volatile("cp.async.commit_group;" ::: "memory")
#define CP_WAIT(n)  asm volatile("cp.async.wait_group %0;" :: "n"(n) : "memory")

__device__ __forceinline__ void ldsm4(uint32_t& r0, uint32_t& r1,
                                      uint32_t& r2, uint32_t& r3, uint32_t addr) {
    asm volatile("ldmatrix.sync.aligned.m8n8.x4.shared.b16 {%0,%1,%2,%3}, [%4];"
                 : "=r"(r0), "=r"(r1), "=r"(r2), "=r"(r3) : "r"(addr));
}

// m16n8k16 fp16 mma, fp32 accum
__device__ __forceinline__ void mma_f16(float* c, const uint32_t* a,
                                        uint32_t b0, uint32_t b1) {
    asm volatile(
        "mma.sync.aligned.m16n8k16.row.col.f32.f16.f16.f32 "
        "{%0,%1,%2,%3}, {%4,%5,%6,%7}, {%8,%9}, {%0,%1,%2,%3};"
        : "+f"(c[0]), "+f"(c[1]), "+f"(c[2]), "+f"(c[3])
        : "r"(a[0]), "r"(a[1]), "r"(a[2]), "r"(a[3]), "r"(b0), "r"(b1));
}

// ---------------- GEMM tile (device) — R12 core ----------------
// [128,128] tile at (rowBase,colBase) of D[M,4096] = A[M,K] @ BT[4096,K]^T
// 16 warps: warpM = wid&3 (rows), warpN = wid>>2 (cols); warp tile 32x32.
// MODE 0: OutF = acc (fp32)                                   (c0)
// MODE 1: v = clip(0.5*Sold + C0q + 0.25*acc)                 (s1; C0q = 0.25*c0)
// MODE 2: v = clip(0.5*Sold + 0.25*(acc + s3old@bw2))         (s2)
// FINAL=false: OutH = h(v);  FINAL=true: fOut[row*OUTW + fColOff + col] = v (fp32)
template <int MODE, bool FINAL>
__device__ __forceinline__ void gemm_tile(
    const __half* __restrict__ A, const __half* __restrict__ BT, int K,
    float* __restrict__ OutF, __half* __restrict__ OutH,
    const __half* __restrict__ Sold, const __half* __restrict__ C0q,
    const float* __restrict__ s3old, const float* __restrict__ bw2,
    float* __restrict__ fOut, int fColOff,
    int rowBase, int colBase, __half* smem)
{
    const int tid  = threadIdx.x;
    const int lane = tid & 31;
    const int wid  = tid >> 5;              // 0..15
    const int g = lane >> 2, q = lane & 3;
    const int warpM = wid & 3;              // 4 row-groups of 32
    const int warpN = wid >> 2;             // 4 col-groups of 32

    float acc[2][4][4];
#pragma unroll
    for (int mi = 0; mi < 2; mi++)
#pragma unroll
        for (int ni = 0; ni < 4; ni++)
#pragma unroll
            for (int t = 0; t < 4; t++) acc[mi][ni][t] = 0.0f;

    // loaders: 512 threads, row = tid>>2, 2 of 8 16B-segments each for A and B
    const int ldr  = tid >> 2;              // 0..127
    const int seg0 = (tid & 3) * 2;         // 0,2,4,6

    const __half* Ag = A  + (size_t)(rowBase + ldr) * K;
    const __half* Bg = BT + (size_t)(colBase + ldr) * K;

    const int nIt = K / BKK;

#define LOAD_STAGE(s, kt)                                            \
    do {                                                             \
        __half* As_ = smem + (s) * STAGE_HALFS;                      \
        __half* Bs_ = As_ + 128 * ROWH;                              \
        uint32_t dA = smem_u32(As_ + ldr * ROWH);                    \
        uint32_t dB = smem_u32(Bs_ + ldr * ROWH);                    \
        _Pragma("unroll")                                            \
        for (int u = 0; u < 2; u++) {                                \
            int sg = seg0 + u;                                       \
            cp16(dA + sg * 16, Ag + (kt) + sg * 8);                  \
            cp16(dB + sg * 16, Bg + (kt) + sg * 8);                  \
        }                                                            \
    } while (0)

    LOAD_STAGE(0, 0);       CP_COMMIT();
    LOAD_STAGE(1, BKK);     CP_COMMIT();
    LOAD_STAGE(2, 2 * BKK); CP_COMMIT();

    const int lrow = (lane & 7) + ((lane >> 3) & 1) * 8;
    const int lcolB = ((lane >> 4) & 1) * 16;   // bytes

    uint32_t a[2][2][4];   // [buf][mi][frag]
    uint32_t b[2][2][4];   // [buf][nj][frag]

#define LOAD_FRAGS(buf, aB, bB, ko)                                          \
    do {                                                                     \
        _Pragma("unroll")                                                    \
        for (int mi = 0; mi < 2; mi++)                                       \
            ldsm4(a[buf][mi][0], a[buf][mi][1], a[buf][mi][2], a[buf][mi][3],\
                  (aB) + mi * 16 * (ROWH * 2) + (ko));                       \
        _Pragma("unroll")                                                    \
        for (int nj = 0; nj < 2; nj++)                                       \
            ldsm4(b[buf][nj][0], b[buf][nj][1], b[buf][nj][2], b[buf][nj][3],\
                  (bB) + nj * 16 * (ROWH * 2) + (ko));                       \
    } while (0)

#define DO_MMA(buf)                                                          \
    do {                                                                     \
        _Pragma("unroll")                                                    \
        for (int nj = 0; nj < 2; nj++) {                                     \
            mma_f16(acc[0][nj * 2 + 0], a[buf][0], b[buf][nj][0], b[buf][nj][2]); \
            mma_f16(acc[0][nj * 2 + 1], a[buf][0], b[buf][nj][1], b[buf][nj][3]); \
            mma_f16(acc[1][nj * 2 + 0], a[buf][1], b[buf][nj][0], b[buf][nj][2]); \
            mma_f16(acc[1][nj * 2 + 1], a[buf][1], b[buf][nj][1], b[buf][nj][3]); \
        }                                                                    \
    } while (0)

    // prime: wait for stage 0, load its first k-step fragments
    CP_WAIT(2);
    __syncthreads();
    {
        const __half* As = smem;
        const __half* Bs = As + 128 * ROWH;
        const uint32_t aB = smem_u32(As + (warpM * 32 + lrow) * ROWH) + lcolB;
        const uint32_t bB = smem_u32(Bs + (warpN * 32 + lrow) * ROWH) + lcolB;
        LOAD_FRAGS(0, aB, bB, 0);
    }

    for (int it = 0; it < nIt; ++it) {
        if (it + 3 < nIt) {
            LOAD_STAGE((it + 3) & (NSTAGE - 1), (it + 3) * BKK);
        }
        CP_COMMIT();

        const __half* As = smem + (it & (NSTAGE - 1)) * STAGE_HALFS;
        const __half* Bs = As + 128 * ROWH;
        const uint32_t aB = smem_u32(As + (warpM * 32 + lrow) * ROWH) + lcolB;
        const uint32_t bB = smem_u32(Bs + (warpN * 32 + lrow) * ROWH) + lcolB;

        // k-steps 0..2: prefetch ks+1 into other buffer, then mma current
#pragma unroll
        for (int ks = 0; ks < 3; ks++) {
            LOAD_FRAGS((ks + 1) & 1, aB, bB, (ks + 1) * 32);
            DO_MMA(ks & 1);
        }

        // boundary: advance smem pipeline, prefetch next stage's k-step 0
        if (it + 1 < nIt) {
            CP_WAIT(2);
            __syncthreads();
            const __half* As2 = smem + ((it + 1) & (NSTAGE - 1)) * STAGE_HALFS;
            const __half* Bs2 = As2 + 128 * ROWH;
            const uint32_t aB2 = smem_u32(As2 + (warpM * 32 + lrow) * ROWH) + lcolB;
            const uint32_t bB2 = smem_u32(Bs2 + (warpN * 32 + lrow) * ROWH) + lcolB;
            LOAD_FRAGS(0, aB2, bB2, 0);
        }
        DO_MMA(1);   // k-step 3 lives in buffer 1
    }
#undef LOAD_FRAGS
#undef DO_MMA
#undef LOAD_STAGE

    // ---------------- epilogue ----------------
    const int rw = rowBase + warpM * 32;
    const int cw = colBase + warpN * 32;

    if (MODE == 2) {
        float s3r[2][2][10];
#pragma unroll
        for (int mi = 0; mi < 2; mi++)
#pragma unroll
            for (int h = 0; h < 2; h++) {
                const int r = rw + mi * 16 + h * 8 + g;
#pragma unroll
                for (int k = 0; k < NOUT; k++)
                    s3r[mi][h][k] = s3old[r * NOUT + k];
            }
#pragma unroll
        for (int ni = 0; ni < 4; ni++) {
            const int cb = cw + ni * 8 + q * 2;
#pragma unroll
            for (int k = 0; k < NOUT; k++) {
                const float2 b2 = *(const float2*)&bw2[(size_t)k * HID + cb];
#pragma unroll
                for (int mi = 0; mi < 2; mi++) {
                    acc[mi][ni][0] = fmaf(s3r[mi][0][k], b2.x, acc[mi][ni][0]);
                    acc[mi][ni][1] = fmaf(s3r[mi][0][k], b2.y, acc[mi][ni][1]);
                    acc[mi][ni][2] = fmaf(s3r[mi][1][k], b2.x, acc[mi][ni][2]);
                    acc[mi][ni][3] = fmaf(s3r[mi][1][k], b2.y, acc[mi][ni][3]);
                }
            }
        }
    }

#pragma unroll
    for (int mi = 0; mi < 2; mi++) {
#pragma unroll
        for (int ni = 0; ni < 4; ni++) {
            const int r0 = rw + mi * 16 + g;
            const int cb = cw + ni * 8 + q * 2;
#pragma unroll
            for (int h = 0; h < 2; h++) {
                const int row = r0 + h * 8;
                const size_t idx = (size_t)row * HID + cb;
                float vx = acc[mi][ni][h * 2 + 0];
                float vy = acc[mi][ni][h * 2 + 1];
                if (MODE == 0) {
                    *(float2*)&OutF[idx] = make_float2(vx, vy);
                } else {
                    const float2 so = __half22float2(*(const __half2*)&Sold[idx]);
                    if (MODE == 1) {
                        const float2 c2 = __half22float2(*(const __half2*)&C0q[idx]);
                        vx = 0.5f * so.x + c2.x + 0.25f * vx;
                        vy = 0.5f * so.y + c2.y + 0.25f * vy;
                    } else {
                        vx = 0.5f * so.x + 0.25f * vx;
                        vy = 0.5f * so.y + 0.25f * vy;
                    }
                    vx = fminf(fmaxf(vx, 0.0f), 1.0f);
                    vy = fminf(fmaxf(vy, 0.0f), 1.0f);
                    if (FINAL) {
                        *(float2*)&fOut[(size_t)row * OUTW + fColOff + cb] =
                            make_float2(vx, vy);
                    } else {
                        *(__half2*)&OutH[idx] = __floats2half2_rn(vx, vy);
                    }
                }
            }
        }
    }
}

// ---------------- s3 tile (device): 32 rows, 512 threads ----------------
template <bool FINAL>
__device__ __forceinline__ void s3_tile(
    const __half* __restrict__ s2old, const float* __restrict__ fw2,
    const float* __restrict__ s3old, const float* __restrict__ y,
    float* __restrict__ s3new, float* __restrict__ fOut,
    int weak, int rowBase, __half* smem_raw)
{
    const int tid = threadIdx.x, lane = tid & 31, wid = tid >> 5;   // 16 warps
    float* fs = (float*)smem_raw;
    float acc[2][NOUT];
#pragma unroll
    for (int r = 0; r < 2; r++)
#pragma unroll
        for (int j = 0; j < NOUT; j++) acc[r][j] = 0.0f;

    for (int c = 0; c < 8; c++) {
        __syncthreads();
        for (int i = tid; i < 512 * NOUT; i += NTHREADS) {
            int kl = i / NOUT, j = i - kl * NOUT;
            fs[kl * 11 + j] = fw2[(size_t)(c * 512 + kl) * NOUT + j];
        }
        __syncthreads();
#pragma unroll
        for (int r = 0; r < 2; r++) {
            const int row = rowBase + wid * 2 + r;
            const __half* s2r = s2old + (size_t)row * HID + c * 512;
#pragma unroll 4
            for (int i = 0; i < 16; i++) {
                const int kl = lane + i * 32;
                const float sv = __half2float(s2r[kl]);
#pragma unroll
                for (int j = 0; j < NOUT; j++)
                    acc[r][j] = fmaf(sv, fs[kl * 11 + j], acc[r][j]);
            }
        }
    }

#pragma unroll
    for (int r = 0; r < 2; r++) {
        const int row = rowBase + wid * 2 + r;
#pragma unroll
        for (int j = 0; j < NOUT; j++) {
            float v = acc[r][j];
#pragma unroll
            for (int o = 16; o; o >>= 1) v += __shfl_xor_sync(0xffffffffu, v, o);
            if (lane == 0) {
                float out = weak ? 0.5f * (v + y[row * NOUT + j])
                                 : 0.5f * (s3old[row * NOUT + j] + v);
                out = fminf(fmaxf(out, 0.0f), 1.0f);
                if (FINAL) fOut[(size_t)row * OUTW + 2 * HID + j] = out;
                else       s3new[row * NOUT + j] = out;
            }
        }
    }
}

// ---------------- fused step kernel: 136 CTAs = one wave ----------------
template <bool FINAL>
__global__ __launch_bounds__(NTHREADS, 1) void step_kernel(
    const __half* __restrict__ s1old, const __half* __restrict__ s2old,
    const float* __restrict__ s3old,
    __half* __restrict__ s1new, __half* __restrict__ s2new, float* __restrict__ s3new,
    const __half* __restrict__ fw1T, const __half* __restrict__ bw1T,
    const float* __restrict__ bw2, const float* __restrict__ fw2,
    const __half* __restrict__ c0q, const float* __restrict__ y,
    float* __restrict__ fOut, int weak)
{
    extern __shared__ __half smem[];
    const int bid = blockIdx.x;
    if (bid < 64) {
        gemm_tile<1, FINAL>(s2old, bw1T, HID, nullptr, s1new, s1old, c0q, nullptr,
                            nullptr, fOut, 0,
                            (bid >> 5) * 128, (bid & 31) * 128, smem);
    } else if (bid < 128) {
        const int t = bid - 64;
        gemm_tile<2, FINAL>(s1old, fw1T, HID, nullptr, s2new, s2old, nullptr, s3old,
                            bw2, fOut, HID,
                            (t >> 5) * 128, (t & 31) * 128, smem);
    } else {
        s3_tile<FINAL>(s2old, fw2, s3old, y, s3new, fOut, weak, (bid - 128) * 32, smem);
    }
}

__global__ __launch_bounds__(NTHREADS, 1) void c0_kernel(
    const __half* __restrict__ rx, const __half* __restrict__ fw0T,
    float* __restrict__ c0)
{
    extern __shared__ __half smem[];
    const int bid = blockIdx.x;
    gemm_tile<0, false>(rx, fw0T, NIN, c0, nullptr, nullptr, nullptr, nullptr,
                        nullptr, nullptr, 0,
                        (bid >> 5) * 128, (bid & 31) * 128, smem);
}

// ---------------- small kernels ----------------
__global__ void clip_kernel(const float* __restrict__ x, __half* __restrict__ rx, int n) {
    int i = blockIdx.x * blockDim.x + threadIdx.x;
    if (i < n) rx[i] = __float2half_rn(fminf(fmaxf(x[i], 0.0f), 1.0f));
}

__global__ void init_kernel(const float* __restrict__ c0, __half* __restrict__ c0q,
                            __half* __restrict__ s1, __half* __restrict__ s2,
                            float* __restrict__ s3) {
    int i = blockIdx.x * blockDim.x + threadIdx.x;
    if (i < BSZ * HID) {
        float qc = 0.25f * c0[i];
        c0q[i] = __float2half_rn(qc);
        s1[i] = __float2half_rn(fminf(fmaxf(qc, 0.0f), 1.0f));
        s2[i] = __half(0.0f);
    }
    if (i < BSZ * NOUT) s3[i] = 0.0f;
}

// fused 64x64-tile transpose+convert for all three weight matrices.
// grid: x = 64 (col tiles of 4096), y = 16 (fw0) + 64 (fw1) + 64 (bw1) = 144.
__global__ void transpose3_kernel(const float* __restrict__ fw0, __half* __restrict__ fw0T,
                                  const float* __restrict__ fw1, __half* __restrict__ fw1T,
                                  const float* __restrict__ bw1, __half* __restrict__ bw1T)
{
    __shared__ float tile[64][65];
    const float* src;
    __half* dst;
    int R, yTile = blockIdx.y;
    if (yTile < 16)        { src = fw0; dst = fw0T; R = NIN; }
    else if (yTile < 80)   { src = fw1; dst = fw1T; R = HID; yTile -= 16; }
    else                   { src = bw1; dst = bw1T; R = HID; yTile -= 80; }
    const int C = HID;

    const int bx = blockIdx.x * 64;   // src col tile
    const int by = yTile * 64;        // src row tile
    const int tx = threadIdx.x, ty = threadIdx.y;
#pragma unroll
    for (int j = 0; j < 2; j++)
#pragma unroll
        for (int i = 0; i < 8; i++)
            tile[ty + i * 8][tx + j * 32] =
                src[(size_t)(by + ty + i * 8) * C + bx + tx + j * 32];
    __syncthreads();
#pragma unroll
    for (int i = 0; i < 8; i++) {
        const int cc = bx + ty + i * 8;          // dst row = src col
        const int k = ty + i * 8;
        __half2 v = __floats2half2_rn(tile[tx * 2][k], tile[tx * 2 + 1][k]);
        *(__half2*)&dst[(size_t)cc * R + by + tx * 2] = v;   // dst cols = src rows
    }
}

// ---------------- launch ----------------
extern "C" void kernel_launch(void* const* d_in, const int* in_sizes, int n_in,
                              void* d_out, int out_size)
{
    const float* x   = (const float*)d_in[0];
    const float* fw0 = (const float*)d_in[1];
    const float* fw1 = (const float*)d_in[2];
    const float* fw2 = (const float*)d_in[3];
    // d_in[4] = bw0 (unused by the dynamics)
    const float* bw1 = (const float*)d_in[5];
    const float* bw2 = (const float*)d_in[6];
    const float* y   = (const float*)d_in[7];
    float* out = (float*)d_out;

    cudaFuncSetAttribute(step_kernel<false>, cudaFuncAttributeMaxDynamicSharedMemorySize, SMEM_BYTES);
    cudaFuncSetAttribute(step_kernel<true>,  cudaFuncAttributeMaxDynamicSharedMemorySize, SMEM_BYTES);
    cudaFuncSetAttribute(c0_kernel,          cudaFuncAttributeMaxDynamicSharedMemorySize, SMEM_BYTES);

    __half *rx, *c0q, *s1base, *s2base, *fw0T, *fw1T, *bw1T;
    float *c0, *s3base;
    cudaGetSymbolAddress((void**)&rx, g_rx);
    cudaGetSymbolAddress((void**)&c0, g_c0);
    cudaGetSymbolAddress((void**)&c0q, g_c0q);
    cudaGetSymbolAddress((void**)&s1base, g_s1);
    cudaGetSymbolAddress((void**)&s2base, g_s2);
    cudaGetSymbolAddress((void**)&s3base, g_s3);
    cudaGetSymbolAddress((void**)&fw0T, g_fw0T);
    cudaGetSymbolAddress((void**)&fw1T, g_fw1T);
    cudaGetSymbolAddress((void**)&bw1T, g_bw1T);

    __half* s1p[2] = { s1base, s1base + (size_t)BSZ * HID };
    __half* s2p[2] = { s2base, s2base + (size_t)BSZ * HID };
    float*  s3p[2] = { s3base, s3base + (size_t)BSZ * NOUT };

    // one fused transpose launch for all three weight matrices
    transpose3_kernel<<<dim3(64, 144), dim3(32, 8)>>>(fw0, fw0T, fw1, fw1T, bw1, bw1T);

    clip_kernel<<<(BSZ * NIN + 255) / 256, 256>>>(x, rx, BSZ * NIN);

    // c0 = rx @ fw0 (loop-invariant), fp32 output
    c0_kernel<<<64, NTHREADS, SMEM_BYTES>>>(rx, fw0T, c0);

    // step 0 collapses to elementwise (states start at zero)
    init_kernel<<<(BSZ * HID + 255) / 256, 256>>>(c0, c0q, s1p[1], s2p[1], s3p[1]);

    // steps 1..23 write fp16 state buffers
    for (int t = 1; t < STEPS_TOTAL - 1; t++) {
        const int p = t & 1;
        const int q = 1 - p;
        const int weak = (t >= STEPS_FREE) ? 1 : 0;
        step_kernel<false><<<136, NTHREADS, SMEM_BYTES>>>(
            s1p[p], s2p[p], s3p[p],
            s1p[q], s2p[q], s3p[q],
            fw1T, bw1T, bw2, fw2, c0q, y, nullptr, weak);
    }

    // final step (t = 24) writes fp32 results directly into d_out
    {
        const int t = STEPS_TOTAL - 1;   // 24
        const int p = t & 1;             // 0
        const int q = 1 - p;
        step_kernel<true><<<136, NTHREADS, SMEM_BYTES>>>(
            s1p[p], s2p[p], s3p[p],
            s1p[q], s2p[q], s3p[q],
            fw1T, bw1T, bw2, fw2, c0q, y, out, 1);
    }
}